// round 3
// baseline (speedup 1.0000x reference)
#include <cuda_runtime.h>
#include <cstdint>

#define BB 32
#define LL 4096
#define EE 512
#define HH 512
#define AA 256

#define TM 64   // rows per block (b,l) pairs
#define TK 32   // k-tile

// scratch (allocation-free rule: __device__ globals)
__device__ float g_dec[BB * AA];          // dec_attn + b_enc + b_dec, [B][A]
__device__ float g_scores[BB * LL];       // pre-softmax scores
__device__ float g_partial[BB * 32 * EE]; // weighted-sum partials

// ---------------------------------------------------------------------------
// packed f32x2 helpers (Blackwell fma.rn.f32x2)
// ---------------------------------------------------------------------------
__device__ __forceinline__ unsigned long long pack_dup(float x) {
    unsigned long long r;
    unsigned int u = __float_as_uint(x);
    asm("mov.b64 %0, {%1, %1};" : "=l"(r) : "r"(u));
    return r;
}
__device__ __forceinline__ void fma2(unsigned long long& d,
                                     unsigned long long a,
                                     unsigned long long b) {
    asm("fma.rn.f32x2 %0, %1, %2, %0;" : "+l"(d) : "l"(a), "l"(b));
}
__device__ __forceinline__ float lo32(unsigned long long v) {
    return __uint_as_float((unsigned int)(v & 0xFFFFFFFFull));
}
__device__ __forceinline__ float hi32(unsigned long long v) {
    return __uint_as_float((unsigned int)(v >> 32));
}

// ---------------------------------------------------------------------------
// Kernel 1: g_dec[b][a] = decoder_hidden[b,:] @ W_dec[:,a] + b_enc[a] + b_dec[a]
// ---------------------------------------------------------------------------
__global__ __launch_bounds__(256) void dec_kernel(
    const float* __restrict__ dh, const float* __restrict__ W_dec,
    const float* __restrict__ b_enc, const float* __restrict__ b_dec)
{
    int b = blockIdx.x;
    int a = threadIdx.x;  // 256 threads, one per A column
    __shared__ float sh[HH];
    for (int h = threadIdx.x; h < HH; h += blockDim.x)
        sh[h] = dh[b * HH + h];
    __syncthreads();
    float acc = 0.f;
#pragma unroll 8
    for (int h = 0; h < HH; h++)
        acc = fmaf(sh[h], W_dec[h * AA + a], acc);
    g_dec[b * AA + a] = acc + b_enc[a] + b_dec[a];
}

// ---------------------------------------------------------------------------
// Kernel 2: fused  scores = relu(features@W_enc + g_dec) @ W_v + b_v
// Block = 64 rows x 256 cols, thread microtile 8x8 (f32x2-packed along cols).
// Warp ty owns rows [ty*8, ty*8+8) fully -> warp shuffle reduces the W_v dot.
// ---------------------------------------------------------------------------
__global__ __launch_bounds__(256, 2) void score_kernel(
    const float* __restrict__ features,
    const float* __restrict__ W_enc,
    const float* __restrict__ W_v,
    const float* __restrict__ b_v)
{
    __shared__ float As[TM][TK + 1];   // [row][k], +1 pad -> conflict-free STS
    __shared__ float Bs[TK][AA];       // [k][col]

    const int row0 = blockIdx.x * TM;          // global row in [0, B*L)
    const int b    = row0 / LL;
    const int tid  = threadIdx.x;
    const int tx   = tid & 31;                 // col group (0..31) == lane
    const int ty   = tid >> 5;                 // row group (0..7)  == warp

    unsigned long long acc2[8][4];             // 8 rows x 4 col-pairs
#pragma unroll
    for (int r = 0; r < 8; r++)
#pragma unroll
        for (int j = 0; j < 4; j++) acc2[r][j] = 0ull;

    const float* fbase = features + (size_t)row0 * EE;

    for (int k0 = 0; k0 < EE; k0 += TK) {
        // load A tile: 64 rows x 32 k (float4 global reads, scalar padded STS)
#pragma unroll
        for (int i = 0; i < 2; i++) {
            int idx = tid + i * 256;           // [0,512)
            int r   = idx >> 3;
            int kq  = idx & 7;
            float4 v = *(const float4*)(fbase + (size_t)r * EE + k0 + kq * 4);
            As[r][kq * 4 + 0] = v.x;
            As[r][kq * 4 + 1] = v.y;
            As[r][kq * 4 + 2] = v.z;
            As[r][kq * 4 + 3] = v.w;
        }
        // load B tile: 32 k x 256 cols (float4 in/out)
#pragma unroll
        for (int i = 0; i < 8; i++) {
            int idx = tid + i * 256;           // [0,2048)
            int kr  = idx >> 6;
            int cq  = idx & 63;
            *(float4*)&Bs[kr][cq * 4] =
                *(const float4*)(W_enc + (size_t)(k0 + kr) * AA + cq * 4);
        }
        __syncthreads();

#pragma unroll
        for (int k = 0; k < TK; k++) {
            unsigned long long ap[8];
#pragma unroll
            for (int r = 0; r < 8; r++)
                ap[r] = pack_dup(As[ty * 8 + r][k]);   // broadcast LDS

            ulonglong2 q0 = *(const ulonglong2*)&Bs[k][tx * 8];
            ulonglong2 q1 = *(const ulonglong2*)&Bs[k][tx * 8 + 4];
            unsigned long long bp[4] = {q0.x, q0.y, q1.x, q1.y};

#pragma unroll
            for (int r = 0; r < 8; r++)
#pragma unroll
                for (int j = 0; j < 4; j++)
                    fma2(acc2[r][j], ap[r], bp[j]);
        }
        __syncthreads();
    }

    // epilogue: + dec bias, relu, dot with W_v, warp-reduce, write score
    float dec[8], wv[8];
#pragma unroll
    for (int c = 0; c < 8; c++) {
        dec[c] = g_dec[b * AA + tx * 8 + c];
        wv[c]  = W_v[tx * 8 + c];
    }
    const float bv = b_v[0];

#pragma unroll
    for (int r = 0; r < 8; r++) {
        float p = 0.f;
#pragma unroll
        for (int j = 0; j < 4; j++) {
            float v0 = lo32(acc2[r][j]) + dec[2 * j];
            float v1 = hi32(acc2[r][j]) + dec[2 * j + 1];
            p = fmaf(fmaxf(v0, 0.f), wv[2 * j], p);
            p = fmaf(fmaxf(v1, 0.f), wv[2 * j + 1], p);
        }
#pragma unroll
        for (int off = 16; off; off >>= 1)
            p += __shfl_xor_sync(0xFFFFFFFFu, p, off);
        if (tx == 0)
            g_scores[row0 + ty * 8 + r] = p + bv;
    }
}

// ---------------------------------------------------------------------------
// Kernel 3: softmax over L per batch; writes attn_weights to d_out tail
// ---------------------------------------------------------------------------
__global__ __launch_bounds__(1024) void softmax_kernel(float* __restrict__ attn)
{
    int b = blockIdx.x;
    const float* s = g_scores + (size_t)b * LL;
    float* w = attn + (size_t)b * LL;
    __shared__ float red1[32];
    __shared__ float red2[32];
    int tid = threadIdx.x;

    float m = -1e30f;
    for (int i = tid; i < LL; i += 1024) m = fmaxf(m, s[i]);
#pragma unroll
    for (int o = 16; o; o >>= 1) m = fmaxf(m, __shfl_xor_sync(~0u, m, o));
    if ((tid & 31) == 0) red1[tid >> 5] = m;
    __syncthreads();
    if (tid < 32) {
        float v = red1[tid];
#pragma unroll
        for (int o = 16; o; o >>= 1) v = fmaxf(v, __shfl_xor_sync(~0u, v, o));
        if (tid == 0) red1[0] = v;
    }
    __syncthreads();
    const float M = red1[0];

    float sum = 0.f;
    for (int i = tid; i < LL; i += 1024) sum += __expf(s[i] - M);
#pragma unroll
    for (int o = 16; o; o >>= 1) sum += __shfl_xor_sync(~0u, sum, o);
    if ((tid & 31) == 0) red2[tid >> 5] = sum;
    __syncthreads();
    if (tid < 32) {
        float v = red2[tid];
#pragma unroll
        for (int o = 16; o; o >>= 1) v += __shfl_xor_sync(~0u, v, o);
        if (tid == 0) red2[0] = v;
    }
    __syncthreads();
    const float inv = 1.f / red2[0];

    for (int i = tid; i < LL; i += 1024)
        w[i] = __expf(s[i] - M) * inv;
}

// ---------------------------------------------------------------------------
// Kernel 4a: partial weighted sums (deterministic, no atomics)
// block (chunk=x in [0,32), b=y): 128 L-rows, 512 threads = one e each
// ---------------------------------------------------------------------------
__global__ __launch_bounds__(512) void wsum_partial(
    const float* __restrict__ features, const float* __restrict__ attn)
{
    int b = blockIdx.y;
    int chunk = blockIdx.x;
    __shared__ float sw[128];
    if (threadIdx.x < 128)
        sw[threadIdx.x] = attn[(size_t)b * LL + chunk * 128 + threadIdx.x];
    __syncthreads();

    float acc = 0.f;
    const float* f = features + ((size_t)b * LL + (size_t)chunk * 128) * EE
                     + threadIdx.x;
#pragma unroll 8
    for (int i = 0; i < 128; i++)
        acc = fmaf(f[(size_t)i * EE], sw[i], acc);
    g_partial[((size_t)b * 32 + chunk) * EE + threadIdx.x] = acc;
}

// Kernel 4b: reduce 32 partials -> output[b,e]
__global__ __launch_bounds__(256) void wsum_reduce(float* __restrict__ out)
{
    int idx = blockIdx.x * 256 + threadIdx.x;  // [0, B*E)
    int b = idx / EE;
    int e = idx - b * EE;
    float acc = 0.f;
#pragma unroll
    for (int c = 0; c < 32; c++)
        acc += g_partial[((size_t)b * 32 + c) * EE + e];
    out[idx] = acc;
}

// ---------------------------------------------------------------------------
extern "C" void kernel_launch(void* const* d_in, const int* in_sizes, int n_in,
                              void* d_out, int out_size)
{
    const float* features = (const float*)d_in[0];
    const float* dh       = (const float*)d_in[1];
    const float* W_enc    = (const float*)d_in[2];
    const float* b_enc    = (const float*)d_in[3];
    const float* W_dec    = (const float*)d_in[4];
    const float* b_dec    = (const float*)d_in[5];
    const float* W_v      = (const float*)d_in[6];
    const float* b_v      = (const float*)d_in[7];

    float* out  = (float*)d_out;         // [B,E] = 16384 floats
    float* attn = out + BB * EE;         // [B,L] = 131072 floats

    dec_kernel<<<BB, 256>>>(dh, W_dec, b_enc, b_dec);
    score_kernel<<<(BB * LL) / TM, 256>>>(features, W_enc, W_v, b_v);
    softmax_kernel<<<BB, 1024>>>(attn);
    wsum_partial<<<dim3(32, BB), 512>>>(features, attn);
    wsum_reduce<<<(BB * EE) / 256, 256>>>(out);
}

// round 5
// speedup vs baseline: 2.1231x; 2.1231x over previous
#include <cuda_runtime.h>
#include <cuda_bf16.h>
#include <cstdint>

#define BB 32
#define LL 4096
#define EE 512
#define HH 512
#define AA 256

// ---------------- scratch (__device__ globals; no allocs allowed) ----------
__device__ float g_dec[BB * AA];                 // dec_attn + b_enc + b_dec
__device__ float g_scores[BB * LL];              // pre-softmax scores
__device__ float g_partial[BB * 64 * EE];        // weighted-sum partials
__device__ __nv_bfloat16 g_Bhi[AA * EE];         // W_enc^T hi, [a][k] K-major
__device__ __nv_bfloat16 g_Blo[AA * EE];         // W_enc^T lo

// ---------------- family-portable PTX helpers ------------------------------
__device__ __forceinline__ uint32_t smem_u32(const void* p) {
    uint32_t a;
    asm("{ .reg .u64 t; cvta.to.shared.u64 t, %1; cvt.u32.u64 %0, t; }"
        : "=r"(a) : "l"(p));
    return a;
}
__device__ __forceinline__ uint32_t pack_bf16x2(float lo, float hi) {
    uint32_t r;
    asm("cvt.rn.bf16x2.f32 %0, %1, %2;" : "=r"(r) : "f"(hi), "f"(lo));
    return r;
}
#define LDSM4(r, addr)                                                        \
    asm volatile("ldmatrix.sync.aligned.m8n8.x4.shared.b16 {%0,%1,%2,%3}, [%4];" \
        : "=r"((r)[0]), "=r"((r)[1]), "=r"((r)[2]), "=r"((r)[3]) : "r"(addr))

#define MMA_BF16(d, a, b0, b1)                                                \
    asm volatile("mma.sync.aligned.m16n8k16.row.col.f32.bf16.bf16.f32 "       \
        "{%0,%1,%2,%3}, {%4,%5,%6,%7}, {%8,%9}, {%0,%1,%2,%3};"               \
        : "+f"((d)[0]), "+f"((d)[1]), "+f"((d)[2]), "+f"((d)[3])              \
        : "r"((a)[0]), "r"((a)[1]), "r"((a)[2]), "r"((a)[3]),                 \
          "r"(b0), "r"(b1))

#define CP16(dst, src)                                                        \
    asm volatile("cp.async.cg.shared.global [%0], [%1], 16;"                  \
        :: "r"(dst), "l"(src) : "memory")
#define CP_COMMIT() asm volatile("cp.async.commit_group;" ::: "memory")
#define CP_WAIT0()  asm volatile("cp.async.wait_group 0;" ::: "memory")
#define CP_WAIT1()  asm volatile("cp.async.wait_group 1;" ::: "memory")

// ---------------- SMEM layout for score kernel (bytes) ---------------------
#define OFF_DEC 0            // 256 f32
#define OFF_WV  1024         // 256 f32
#define OFF_RED 2048         // 128*4 f32
#define OFF_AHI 4096         // 128 x 32 bf16, stride 40
#define OFF_ALO 14336
#define OFF_B0  24576        // B double buffer: [hi 20480][lo 20480] x2
#define B_BUF_STRIDE 40960
#define B_LO_OFF 20480
#define SA 40                // padded k-stride (elems) -> conflict-free ldmatrix
#define SMEM_BYTES 106496

// ---------------------------------------------------------------------------
// Prep: split W_enc into K-major bf16 hi/lo  (g_B*[a][k])
// ---------------------------------------------------------------------------
__global__ __launch_bounds__(256) void prep_b(const float* __restrict__ W_enc)
{
    int idx = blockIdx.x * 256 + threadIdx.x;   // [0, AA*EE)
    int a = idx >> 9, k = idx & 511;
    float f = W_enc[(size_t)k * AA + a];
    __nv_bfloat16 h = __float2bfloat16(f);
    g_Bhi[idx] = h;
    g_Blo[idx] = __float2bfloat16(f - __bfloat162float(h));
}

// ---------------------------------------------------------------------------
// dec projection: g_dec[b][a] = dh@W_dec + b_enc + b_dec
// ---------------------------------------------------------------------------
__global__ __launch_bounds__(256) void dec_kernel(
    const float* __restrict__ dh, const float* __restrict__ W_dec,
    const float* __restrict__ b_enc, const float* __restrict__ b_dec)
{
    int b = blockIdx.x, a = threadIdx.x;
    __shared__ float sh[HH];
    for (int h = threadIdx.x; h < HH; h += 256) sh[h] = dh[b * HH + h];
    __syncthreads();
    float acc = 0.f;
#pragma unroll 8
    for (int h = 0; h < HH; h++) acc = fmaf(sh[h], W_dec[h * AA + a], acc);
    g_dec[b * AA + a] = acc + b_enc[a] + b_dec[a];
}

// ---------------------------------------------------------------------------
// Fused score GEMM on mma.sync (bf16 3-term split):
//   D[128,256] = feats_tile @ W_enc ; score = sum_a relu(D+dec)*wv + bv
// 512 threads (4x4 warps, warp tile 32x64), K chunks of 32,
// A: reg-prefetch + in-register fp32->bf16 hi/lo split; B: cp.async dbl-buffer.
// ---------------------------------------------------------------------------
__global__ __launch_bounds__(512, 1) void score_kernel(
    const float* __restrict__ features,
    const float* __restrict__ W_v,
    const float* __restrict__ b_v)
{
    extern __shared__ __align__(16) char smem[];
    const uint32_t sb = smem_u32(smem);

    const int tid  = threadIdx.x;
    const int lane = tid & 31;
    const int wid  = tid >> 5;
    const int warp_m = wid & 3;        // 0..3 -> rows warp_m*32
    const int warp_n = wid >> 2;       // 0..3 -> cols warp_n*64
    const int row0 = blockIdx.x * 128;
    const int b    = row0 >> 12;

    float* sdec = (float*)(smem + OFF_DEC);
    float* swv  = (float*)(smem + OFF_WV);
    float* sred = (float*)(smem + OFF_RED);
    if (tid < 256) {
        sdec[tid] = g_dec[b * AA + tid];
        swv[tid]  = W_v[tid];
    }

    // lane-constant ldmatrix addresses
    const int m_base = warp_m * 32;
    const int n_base = warp_n * 64;
    const uint32_t aoff =
        (uint32_t)((m_base + (lane & 15)) * SA + (lane >> 4) * 8) * 2;
    const uint32_t aHi = sb + OFF_AHI + aoff;
    const uint32_t aLo = sb + OFF_ALO + aoff;
    const uint32_t boff =
        (uint32_t)((n_base + (lane >> 4) * 8 + (lane & 7)) * SA +
                   ((lane >> 3) & 1) * 8) * 2;

    float d[2][8][4];
#pragma unroll
    for (int mt = 0; mt < 2; mt++)
#pragma unroll
        for (int nt = 0; nt < 8; nt++)
#pragma unroll
            for (int q = 0; q < 4; q++) d[mt][nt][q] = 0.f;

    // A prefetch pointer: thread covers row tid/4, float4 cols (tid%4)*2+{0,1}
    const float4* f4 = (const float4*)features +
                       ((size_t)row0 + (tid >> 2)) * 128 + (tid & 3) * 2;

    // prologue: B chunk 0 via cp.async, A chunk 0 into regs
    {
        const uint32_t base = sb + OFF_B0;
#pragma unroll
        for (int i = 0; i < 4; i++) {
            int idx = tid + i * 512;
            int which = idx >> 10, rem = idx & 1023;
            int a = rem >> 2, seg = rem & 3;
            uint32_t dst = base + which * B_LO_OFF +
                           (uint32_t)(a * SA + seg * 8) * 2;
            const __nv_bfloat16* src =
                (which ? g_Blo : g_Bhi) + a * EE + seg * 8;
            CP16(dst, src);
        }
        CP_COMMIT();
    }
    float4 ar0 = f4[0], ar1 = f4[1];

    for (int c = 0; c < 16; c++) {
        if (c) __syncthreads();            // buffers free (prev compute done)

        // store A(c): fp32 -> bf16 hi/lo, padded tile
        {
            const int r = tid >> 2;
            const int q0 = (tid & 3) * 2;
            float4 v = ar0;
#pragma unroll
            for (int j = 0; j < 2; j++) {
                float h0 = __bfloat162float(__float2bfloat16(v.x));
                float h1 = __bfloat162float(__float2bfloat16(v.y));
                float h2 = __bfloat162float(__float2bfloat16(v.z));
                float h3 = __bfloat162float(__float2bfloat16(v.w));
                uint32_t off = (uint32_t)(r * SA + (q0 + j) * 4) * 2;
                *(uint2*)(smem + OFF_AHI + off) =
                    make_uint2(pack_bf16x2(h0, h1), pack_bf16x2(h2, h3));
                *(uint2*)(smem + OFF_ALO + off) =
                    make_uint2(pack_bf16x2(v.x - h0, v.y - h1),
                               pack_bf16x2(v.z - h2, v.w - h3));
                v = ar1;
            }
        }

        if (c < 15) {
            // B(c+1) cp.async into other buffer
            const uint32_t base = sb + OFF_B0 + ((c + 1) & 1) * B_BUF_STRIDE;
            const int k0 = (c + 1) * 32;
#pragma unroll
            for (int i = 0; i < 4; i++) {
                int idx = tid + i * 512;
                int which = idx >> 10, rem = idx & 1023;
                int a = rem >> 2, seg = rem & 3;
                uint32_t dst = base + which * B_LO_OFF +
                               (uint32_t)(a * SA + seg * 8) * 2;
                const __nv_bfloat16* src =
                    (which ? g_Blo : g_Bhi) + a * EE + k0 + seg * 8;
                CP16(dst, src);
            }
            CP_COMMIT();
            // A(c+1) into regs (latency hides under compute)
            ar0 = f4[(c + 1) * 8];
            ar1 = f4[(c + 1) * 8 + 1];
            CP_WAIT1();                    // B(c) arrived; B(c+1) in flight
        } else {
            CP_WAIT0();
        }
        __syncthreads();                   // A stores visible + B(c) ready

        // ---- compute chunk c: 2 k16-steps x (2 mt x 8 nt x 3 terms) ------
        const uint32_t bHiBase = sb + OFF_B0 + (c & 1) * B_BUF_STRIDE;
#pragma unroll
        for (int ks = 0; ks < 2; ks++) {
            uint32_t ah[2][4], al[2][4];
#pragma unroll
            for (int mt = 0; mt < 2; mt++) {
                uint32_t ao = (uint32_t)(mt * 16 * SA + ks * 16) * 2;
                LDSM4(ah[mt], aHi + ao);
                LDSM4(al[mt], aLo + ao);
            }
#pragma unroll
            for (int ntp = 0; ntp < 4; ntp++) {
                uint32_t bh[4], bl[4];
                uint32_t bo = boff + (uint32_t)(ntp * 16 * SA + ks * 16) * 2;
                LDSM4(bh, bHiBase + bo);
                LDSM4(bl, bHiBase + B_LO_OFF + bo);
#pragma unroll
                for (int mt = 0; mt < 2; mt++)
#pragma unroll
                    for (int t = 0; t < 2; t++) {
                        float* dd = d[mt][ntp * 2 + t];
                        MMA_BF16(dd, ah[mt], bh[2 * t], bh[2 * t + 1]);
                        MMA_BF16(dd, ah[mt], bl[2 * t], bl[2 * t + 1]);
                        MMA_BF16(dd, al[mt], bh[2 * t], bh[2 * t + 1]);
                    }
            }
        }
    }

    // ---- epilogue: + dec, relu, dot W_v; quad shuffle + 4-way smem reduce --
#pragma unroll
    for (int mt = 0; mt < 2; mt++) {
        float s0 = 0.f, s1 = 0.f;
#pragma unroll
        for (int nt = 0; nt < 8; nt++) {
            int c0 = n_base + nt * 8 + (lane & 3) * 2;
            float e0 = sdec[c0], e1 = sdec[c0 + 1];
            float w0 = swv[c0], w1 = swv[c0 + 1];
            s0 = fmaf(fmaxf(d[mt][nt][0] + e0, 0.f), w0, s0);
            s0 = fmaf(fmaxf(d[mt][nt][1] + e1, 0.f), w1, s0);
            s1 = fmaf(fmaxf(d[mt][nt][2] + e0, 0.f), w0, s1);
            s1 = fmaf(fmaxf(d[mt][nt][3] + e1, 0.f), w1, s1);
        }
        s0 += __shfl_xor_sync(~0u, s0, 1);
        s0 += __shfl_xor_sync(~0u, s0, 2);
        s1 += __shfl_xor_sync(~0u, s1, 1);
        s1 += __shfl_xor_sync(~0u, s1, 2);
        if ((lane & 3) == 0) {
            int r = m_base + mt * 16 + (lane >> 2);
            sred[r * 4 + warp_n] = s0;
            sred[(r + 8) * 4 + warp_n] = s1;
        }
    }
    __syncthreads();
    if (tid < 128) {
        float s = sred[tid * 4] + sred[tid * 4 + 1] +
                  sred[tid * 4 + 2] + sred[tid * 4 + 3];
        g_scores[row0 + tid] = s + b_v[0];
    }
}

// ---------------------------------------------------------------------------
// softmax over L per batch -> attn (d_out tail)
// ---------------------------------------------------------------------------
__global__ __launch_bounds__(1024) void softmax_kernel(float* __restrict__ attn)
{
    int b = blockIdx.x;
    const float* s = g_scores + (size_t)b * LL;
    float* w = attn + (size_t)b * LL;
    __shared__ float red1[32];
    __shared__ float red2[32];
    int tid = threadIdx.x;

    float m = -1e30f;
    for (int i = tid; i < LL; i += 1024) m = fmaxf(m, s[i]);
#pragma unroll
    for (int o = 16; o; o >>= 1) m = fmaxf(m, __shfl_xor_sync(~0u, m, o));
    if ((tid & 31) == 0) red1[tid >> 5] = m;
    __syncthreads();
    if (tid < 32) {
        float v = red1[tid];
#pragma unroll
        for (int o = 16; o; o >>= 1) v = fmaxf(v, __shfl_xor_sync(~0u, v, o));
        if (tid == 0) red1[0] = v;
    }
    __syncthreads();
    const float M = red1[0];

    float sum = 0.f;
    for (int i = tid; i < LL; i += 1024) sum += __expf(s[i] - M);
#pragma unroll
    for (int o = 16; o; o >>= 1) sum += __shfl_xor_sync(~0u, sum, o);
    if ((tid & 31) == 0) red2[tid >> 5] = sum;
    __syncthreads();
    if (tid < 32) {
        float v = red2[tid];
#pragma unroll
        for (int o = 16; o; o >>= 1) v += __shfl_xor_sync(~0u, v, o);
        if (tid == 0) red2[0] = v;
    }
    __syncthreads();
    const float inv = 1.f / red2[0];

    for (int i = tid; i < LL; i += 1024)
        w[i] = __expf(s[i] - M) * inv;
}

// ---------------------------------------------------------------------------
// weighted sum: 64 chunks x 64 L-rows per block (deterministic two-stage)
// ---------------------------------------------------------------------------
__global__ __launch_bounds__(512) void wsum_partial(
    const float* __restrict__ features, const float* __restrict__ attn)
{
    int b = blockIdx.y, chunk = blockIdx.x;
    __shared__ float sw[64];
    if (threadIdx.x < 64)
        sw[threadIdx.x] = attn[(size_t)b * LL + chunk * 64 + threadIdx.x];
    __syncthreads();

    float acc = 0.f;
    const float* f = features + ((size_t)b * LL + (size_t)chunk * 64) * EE
                     + threadIdx.x;
#pragma unroll 16
    for (int i = 0; i < 64; i++)
        acc = fmaf(f[(size_t)i * EE], sw[i], acc);
    g_partial[((size_t)b * 64 + chunk) * EE + threadIdx.x] = acc;
}

__global__ __launch_bounds__(256) void wsum_reduce(float* __restrict__ out)
{
    int idx = blockIdx.x * 256 + threadIdx.x;  // [0, B*E)
    int b = idx / EE, e = idx - b * EE;
    float acc = 0.f;
#pragma unroll
    for (int c = 0; c < 64; c++)
        acc += g_partial[((size_t)b * 64 + c) * EE + e];
    out[idx] = acc;
}

// ---------------------------------------------------------------------------
extern "C" void kernel_launch(void* const* d_in, const int* in_sizes, int n_in,
                              void* d_out, int out_size)
{
    const float* features = (const float*)d_in[0];
    const float* dh       = (const float*)d_in[1];
    const float* W_enc    = (const float*)d_in[2];
    const float* b_enc    = (const float*)d_in[3];
    const float* W_dec    = (const float*)d_in[4];
    const float* b_dec    = (const float*)d_in[5];
    const float* W_v      = (const float*)d_in[6];
    const float* b_v      = (const float*)d_in[7];

    float* out  = (float*)d_out;        // [B,E]
    float* attn = out + BB * EE;        // [B,L]

    cudaFuncSetAttribute(score_kernel,
                         cudaFuncAttributeMaxDynamicSharedMemorySize,
                         SMEM_BYTES);

    prep_b<<<(AA * EE) / 256, 256>>>(W_enc);
    dec_kernel<<<BB, 256>>>(dh, W_dec, b_enc, b_dec);
    score_kernel<<<(BB * LL) / 128, 512, SMEM_BYTES>>>(features, W_v, b_v);
    softmax_kernel<<<BB, 1024>>>(attn);
    wsum_partial<<<dim3(64, BB), 512>>>(features, attn);
    wsum_reduce<<<(BB * EE) / 256, 256>>>(out);
}

// round 6
// speedup vs baseline: 2.3743x; 1.1183x over previous
#include <cuda_runtime.h>
#include <cuda_fp16.h>
#include <cstdint>

#define BB 32
#define LL 4096
#define EE 512
#define HH 512
#define AA 256

// ---------------- scratch (__device__ globals; no allocs allowed) ----------
__device__ float g_dec[BB * AA];                 // dec_attn + b_enc + b_dec
__device__ float g_scores[BB * LL];              // pre-softmax scores
__device__ float g_partial[BB * 64 * EE];        // weighted-sum partials
__device__ __half g_Bhi[AA * EE];                // W_enc^T hi, [a][k] K-major
__device__ __half g_Blo[AA * EE];                // W_enc^T lo

// ---------------- family-portable PTX helpers ------------------------------
__device__ __forceinline__ uint32_t smem_u32(const void* p) {
    uint32_t a;
    asm("{ .reg .u64 t; cvta.to.shared.u64 t, %1; cvt.u32.u64 %0, t; }"
        : "=r"(a) : "l"(p));
    return a;
}
__device__ __forceinline__ uint32_t pack_h2(float lo, float hi) {
    uint32_t r;
    asm("cvt.rn.f16x2.f32 %0, %1, %2;" : "=r"(r) : "f"(hi), "f"(lo));
    return r;
}
#define LDSM4(r, addr)                                                        \
    asm volatile("ldmatrix.sync.aligned.m8n8.x4.shared.b16 {%0,%1,%2,%3}, [%4];" \
        : "=r"((r)[0]), "=r"((r)[1]), "=r"((r)[2]), "=r"((r)[3]) : "r"(addr))

#define MMA_F16(d, a, b0, b1)                                                 \
    asm volatile("mma.sync.aligned.m16n8k16.row.col.f32.f16.f16.f32 "         \
        "{%0,%1,%2,%3}, {%4,%5,%6,%7}, {%8,%9}, {%0,%1,%2,%3};"               \
        : "+f"((d)[0]), "+f"((d)[1]), "+f"((d)[2]), "+f"((d)[3])              \
        : "r"((a)[0]), "r"((a)[1]), "r"((a)[2]), "r"((a)[3]),                 \
          "r"(b0), "r"(b1))

#define CP16(dst, src)                                                        \
    asm volatile("cp.async.cg.shared.global [%0], [%1], 16;"                  \
        :: "r"(dst), "l"(src) : "memory")
#define CP_COMMIT() asm volatile("cp.async.commit_group;" ::: "memory")
#define CP_WAIT0()  asm volatile("cp.async.wait_group 0;" ::: "memory")
#define CP_WAIT1()  asm volatile("cp.async.wait_group 1;" ::: "memory")

// ---------------- SMEM layout for score kernel (bytes) ---------------------
#define SA 72                // padded k-stride (halfs): stride-4 banks, no conflicts
#define OFF_DEC 0            // 256 f32
#define OFF_WV  1024         // 256 f32
#define OFF_RED 2048         // 128*4 f32
#define OFF_A   4096         // A double buffer: 128 x SA halfs each
#define A_STRIDE 18432
#define OFF_B   40960        // B double buffer: [hi][lo], 256 x SA halfs each
#define B_STRIDE 73728
#define B_LO 36864
#define SMEM_BYTES 188416

// ---------------------------------------------------------------------------
// setup: blocks [0,512) split W_enc -> fp16 hi/lo K-major; blocks [512,544) dec
// ---------------------------------------------------------------------------
__global__ __launch_bounds__(256) void setup_kernel(
    const float* __restrict__ W_enc, const float* __restrict__ dh,
    const float* __restrict__ W_dec, const float* __restrict__ b_enc,
    const float* __restrict__ b_dec)
{
    if (blockIdx.x < 512) {
        int idx = blockIdx.x * 256 + threadIdx.x;   // [0, AA*EE)
        int a = idx >> 9, k = idx & 511;
        float f = W_enc[(size_t)k * AA + a];
        __half h = __float2half_rn(f);
        g_Bhi[idx] = h;
        g_Blo[idx] = __float2half_rn(f - __half2float(h));
    } else {
        int b = blockIdx.x - 512, a = threadIdx.x;
        __shared__ float sh[HH];
        for (int h = threadIdx.x; h < HH; h += 256) sh[h] = dh[b * HH + h];
        __syncthreads();
        float acc = 0.f;
#pragma unroll 8
        for (int h = 0; h < HH; h++) acc = fmaf(sh[h], W_dec[h * AA + a], acc);
        g_dec[b * AA + a] = acc + b_enc[a] + b_dec[a];
    }
}

// ---------------------------------------------------------------------------
// Fused score GEMM, fp16 2-term split (D = ah*bh + ah*bl):
//   score = sum_a relu(feats@W_enc + dec)*wv + bv
// 512 thr (4x4 warps, warp tile 32x64), K chunks of 64, A STS inside compute,
// B cp.async prefetch distance 2, double-buffered A and B.
// ---------------------------------------------------------------------------
__global__ __launch_bounds__(512, 1) void score_kernel(
    const float* __restrict__ features,
    const float* __restrict__ W_v,
    const float* __restrict__ b_v)
{
    extern __shared__ __align__(16) char smem[];
    const uint32_t sb = smem_u32(smem);

    const int tid  = threadIdx.x;
    const int lane = tid & 31;
    const int wid  = tid >> 5;
    const int warp_m = wid & 3;
    const int warp_n = wid >> 2;
    const int row0 = blockIdx.x * 128;
    const int b    = row0 >> 12;

    float* sdec = (float*)(smem + OFF_DEC);
    float* swv  = (float*)(smem + OFF_WV);
    float* sred = (float*)(smem + OFF_RED);
    if (tid < 256) {
        sdec[tid] = g_dec[b * AA + tid];
        swv[tid]  = W_v[tid];
    }

    const int m_base = warp_m * 32;
    const int n_base = warp_n * 64;
    const uint32_t aoff =
        (uint32_t)((m_base + (lane & 15)) * SA + (lane >> 4) * 8) * 2;
    const uint32_t boff =
        (uint32_t)((n_base + (lane >> 4) * 8 + (lane & 7)) * SA +
                   ((lane >> 3) & 1) * 8) * 2;

    float d[2][8][4];
#pragma unroll
    for (int mt = 0; mt < 2; mt++)
#pragma unroll
        for (int nt = 0; nt < 8; nt++)
#pragma unroll
            for (int q = 0; q < 4; q++) d[mt][nt][q] = 0.f;

    // A prefetch: thread covers row tid/4, 16 floats at col (tid&3)*16
    const int ar = tid >> 2, aq = tid & 3;
    const float4* f4 = (const float4*)features +
                       ((size_t)row0 + ar) * 128 + aq * 4;
    const uint32_t a_sts = (uint32_t)(ar * SA + aq * 16) * 2;

    float4 fr[4];

    // B cp.async: 8 granules/thread/chunk over hi+lo
    auto cp_b = [&](int chunk) {
        const uint32_t base = sb + OFF_B + (chunk & 1) * B_STRIDE;
        const int k0 = chunk * 64;
#pragma unroll
        for (int i = 0; i < 8; i++) {
            int idx = tid + i * 512;            // [0,4096)
            int which = idx >> 11, rem = idx & 2047;
            int a = rem >> 3, seg = rem & 7;
            uint32_t dst = base + which * B_LO +
                           (uint32_t)(a * SA + seg * 8) * 2;
            const __half* src = (which ? g_Blo : g_Bhi) +
                                (size_t)a * EE + k0 + seg * 8;
            CP16(dst, src);
        }
        CP_COMMIT();
    };
    auto lda = [&](int chunk) {
#pragma unroll
        for (int j = 0; j < 4; j++) fr[j] = f4[chunk * 16 + j];
    };
    auto sts_a = [&](int chunk) {
        char* dst = smem + OFF_A + (chunk & 1) * A_STRIDE + a_sts;
        *(uint4*)dst = make_uint4(
            pack_h2(fr[0].x, fr[0].y), pack_h2(fr[0].z, fr[0].w),
            pack_h2(fr[1].x, fr[1].y), pack_h2(fr[1].z, fr[1].w));
        *(uint4*)(dst + 16) = make_uint4(
            pack_h2(fr[2].x, fr[2].y), pack_h2(fr[2].z, fr[2].w),
            pack_h2(fr[3].x, fr[3].y), pack_h2(fr[3].z, fr[3].w));
    };

    // prologue
    cp_b(0);
    cp_b(1);
    lda(0); sts_a(0);
    lda(1);
    CP_WAIT1();            // B(0) done
    __syncthreads();       // A(0), B(0), dec/wv visible

    for (int c = 0; c < 8; c++) {
        if (c < 7) sts_a(c + 1);           // into idle A buffer
        if (c < 6) lda(c + 2);             // next A into regs (hides DRAM)

        const uint32_t aBase = sb + OFF_A + (c & 1) * A_STRIDE + aoff;
        const uint32_t bBase = sb + OFF_B + (c & 1) * B_STRIDE;
#pragma unroll
        for (int ks = 0; ks < 4; ks++) {
            uint32_t ah[2][4];
#pragma unroll
            for (int mt = 0; mt < 2; mt++)
                LDSM4(ah[mt], aBase + (uint32_t)(mt * 16 * SA + ks * 16) * 2);
#pragma unroll
            for (int ntp = 0; ntp < 4; ntp++) {
                uint32_t bh[4], bl[4];
                uint32_t bo = boff + (uint32_t)(ntp * 16 * SA + ks * 16) * 2;
                LDSM4(bh, bBase + bo);
                LDSM4(bl, bBase + B_LO + bo);
#pragma unroll
                for (int mt = 0; mt < 2; mt++)
#pragma unroll
                    for (int t = 0; t < 2; t++) {
                        float* dd = d[mt][ntp * 2 + t];
                        MMA_F16(dd, ah[mt], bh[2 * t], bh[2 * t + 1]);
                        MMA_F16(dd, ah[mt], bl[2 * t], bl[2 * t + 1]);
                    }
            }
        }
        __syncthreads();                   // B(c) reads + A(c+1) stores done
        if (c < 6) {
            cp_b(c + 2);                   // buffer (c&1) now free
            CP_WAIT1();                    // B(c+1) arrived
            __syncthreads();
        } else if (c == 6) {
            CP_WAIT0();                    // B(7) arrived
            __syncthreads();
        }
    }

    // ---- epilogue: + dec, relu, dot W_v; quad shuffle + 4-way smem reduce --
#pragma unroll
    for (int mt = 0; mt < 2; mt++) {
        float s0 = 0.f, s1 = 0.f;
#pragma unroll
        for (int nt = 0; nt < 8; nt++) {
            int c0 = n_base + nt * 8 + (lane & 3) * 2;
            float e0 = sdec[c0], e1 = sdec[c0 + 1];
            float w0 = swv[c0], w1 = swv[c0 + 1];
            s0 = fmaf(fmaxf(d[mt][nt][0] + e0, 0.f), w0, s0);
            s0 = fmaf(fmaxf(d[mt][nt][1] + e1, 0.f), w1, s0);
            s1 = fmaf(fmaxf(d[mt][nt][2] + e0, 0.f), w0, s1);
            s1 = fmaf(fmaxf(d[mt][nt][3] + e1, 0.f), w1, s1);
        }
        s0 += __shfl_xor_sync(~0u, s0, 1);
        s0 += __shfl_xor_sync(~0u, s0, 2);
        s1 += __shfl_xor_sync(~0u, s1, 1);
        s1 += __shfl_xor_sync(~0u, s1, 2);
        if ((lane & 3) == 0) {
            int r = m_base + mt * 16 + (lane >> 2);
            sred[r * 4 + warp_n] = s0;
            sred[(r + 8) * 4 + warp_n] = s1;
        }
    }
    __syncthreads();
    if (tid < 128) {
        float s = sred[tid * 4] + sred[tid * 4 + 1] +
                  sred[tid * 4 + 2] + sred[tid * 4 + 3];
        g_scores[row0 + tid] = s + b_v[0];
    }
}

// ---------------------------------------------------------------------------
// softmax over L per batch -> attn (d_out tail)
// ---------------------------------------------------------------------------
__global__ __launch_bounds__(1024) void softmax_kernel(float* __restrict__ attn)
{
    int b = blockIdx.x;
    const float* s = g_scores + (size_t)b * LL;
    float* w = attn + (size_t)b * LL;
    __shared__ float red1[32];
    __shared__ float red2[32];
    int tid = threadIdx.x;

    float m = -1e30f;
    for (int i = tid; i < LL; i += 1024) m = fmaxf(m, s[i]);
#pragma unroll
    for (int o = 16; o; o >>= 1) m = fmaxf(m, __shfl_xor_sync(~0u, m, o));
    if ((tid & 31) == 0) red1[tid >> 5] = m;
    __syncthreads();
    if (tid < 32) {
        float v = red1[tid];
#pragma unroll
        for (int o = 16; o; o >>= 1) v = fmaxf(v, __shfl_xor_sync(~0u, v, o));
        if (tid == 0) red1[0] = v;
    }
    __syncthreads();
    const float M = red1[0];

    float sum = 0.f;
    for (int i = tid; i < LL; i += 1024) sum += __expf(s[i] - M);
#pragma unroll
    for (int o = 16; o; o >>= 1) sum += __shfl_xor_sync(~0u, sum, o);
    if ((tid & 31) == 0) red2[tid >> 5] = sum;
    __syncthreads();
    if (tid < 32) {
        float v = red2[tid];
#pragma unroll
        for (int o = 16; o; o >>= 1) v += __shfl_xor_sync(~0u, v, o);
        if (tid == 0) red2[0] = v;
    }
    __syncthreads();
    const float inv = 1.f / red2[0];

    for (int i = tid; i < LL; i += 1024)
        w[i] = __expf(s[i] - M) * inv;
}

// ---------------------------------------------------------------------------
// weighted sum: 64 chunks x 64 L-rows per block, 4 accumulators for MLP
// ---------------------------------------------------------------------------
__global__ __launch_bounds__(512) void wsum_partial(
    const float* __restrict__ features, const float* __restrict__ attn)
{
    int b = blockIdx.y, chunk = blockIdx.x;
    __shared__ float sw[64];
    if (threadIdx.x < 64)
        sw[threadIdx.x] = attn[(size_t)b * LL + chunk * 64 + threadIdx.x];
    __syncthreads();

    const float* f = features + ((size_t)b * LL + (size_t)chunk * 64) * EE
                     + threadIdx.x;
    float a0 = 0.f, a1 = 0.f, a2 = 0.f, a3 = 0.f;
#pragma unroll
    for (int i = 0; i < 64; i += 4) {
        float v0 = f[(size_t)(i + 0) * EE];
        float v1 = f[(size_t)(i + 1) * EE];
        float v2 = f[(size_t)(i + 2) * EE];
        float v3 = f[(size_t)(i + 3) * EE];
        a0 = fmaf(v0, sw[i + 0], a0);
        a1 = fmaf(v1, sw[i + 1], a1);
        a2 = fmaf(v2, sw[i + 2], a2);
        a3 = fmaf(v3, sw[i + 3], a3);
    }
    g_partial[((size_t)b * 64 + chunk) * EE + threadIdx.x] =
        (a0 + a1) + (a2 + a3);
}

__global__ __launch_bounds__(256) void wsum_reduce(float* __restrict__ out)
{
    int idx = blockIdx.x * 256 + threadIdx.x;  // [0, B*E)
    int b = idx / EE, e = idx - b * EE;
    float acc = 0.f;
#pragma unroll
    for (int c = 0; c < 64; c++)
        acc += g_partial[((size_t)b * 64 + c) * EE + e];
    out[idx] = acc;
}

// ---------------------------------------------------------------------------
extern "C" void kernel_launch(void* const* d_in, const int* in_sizes, int n_in,
                              void* d_out, int out_size)
{
    const float* features = (const float*)d_in[0];
    const float* dh       = (const float*)d_in[1];
    const float* W_enc    = (const float*)d_in[2];
    const float* b_enc    = (const float*)d_in[3];
    const float* W_dec    = (const float*)d_in[4];
    const float* b_dec    = (const float*)d_in[5];
    const float* W_v      = (const float*)d_in[6];
    const float* b_v      = (const float*)d_in[7];

    float* out  = (float*)d_out;        // [B,E]
    float* attn = out + BB * EE;        // [B,L]

    cudaFuncSetAttribute(score_kernel,
                         cudaFuncAttributeMaxDynamicSharedMemorySize,
                         SMEM_BYTES);

    setup_kernel<<<544, 256>>>(W_enc, dh, W_dec, b_enc, b_dec);
    score_kernel<<<(BB * LL) / 128, 512, SMEM_BYTES>>>(features, W_v, b_v);
    softmax_kernel<<<BB, 1024>>>(attn);
    wsum_partial<<<dim3(64, BB), 512>>>(features, attn);
    wsum_reduce<<<(BB * EE) / 256, 256>>>(out);
}